// round 8
// baseline (speedup 1.0000x reference)
#include <cuda_runtime.h>
#include <cuda_bf16.h>

// NuclearLossFunc: loss = sum(x^2) / (B*C), x: (32,64,256,256) fp32
// = 134,217,728 elements = 512 MiB read. HBM-bound reduction.
//
// R8: DRAM-active is invariably ~68.2us (7.87 TB/s while busy); the
// ~12us idle is CTA finish spread (B300 spr floor 1.10-1.17). R7's
// stealing failed because ONE counter at ~205 steals/us exceeded
// same-address L2-atomic throughput. Fix: WARP-level stealing with 16
// sharded counters (each shard: 2048 x 16KB chunks, one warp per CTA
// -> uniform SM coverage, ~21 steals/us/shard), steal-ahead to hide
// ATOMG latency, zero barriers in the hot path.
// Determinism: fixed tree per chunk; chunk sums in per-lane double
// (steal-order noise ~1e-15); fixed final tree.

#define NBLOCKS   592          // 148 SMs * 4 CTAs, one wave
#define NTHREADS  512          // 16 warps/CTA -> 9472 warps
#define SHARDS    16
#define CPS       2048         // chunks per shard
#define CHUNK_F4  1024         // float4 per chunk = 16KB
#define SEEDS     592          // seeded chunks per shard (= warps/shard)

__device__ double       g_partials[NBLOCKS];
__device__ unsigned int g_count;                 // ticket, zero-init
__device__ int g_ctr[SHARDS] = {
    SEEDS, SEEDS, SEEDS, SEEDS, SEEDS, SEEDS, SEEDS, SEEDS,
    SEEDS, SEEDS, SEEDS, SEEDS, SEEDS, SEEDS, SEEDS, SEEDS
};

__global__ __launch_bounds__(NTHREADS) void sqsum_ws2_kernel(
    const float4* __restrict__ in,
    float* __restrict__ out, float scale)
{
    const int tid  = threadIdx.x;
    const int lane = tid & 31;
    const int wid  = tid >> 5;
    const int gw   = blockIdx.x * (NTHREADS / 32) + wid;   // 0..9471
    const int s    = gw & (SHARDS - 1);
    int rel        = gw >> 4;                              // 0..591 seed

    const float4* shard_base = in + (long long)s * CPS * CHUNK_F4;
    double acc = 0.0;

    while (rel < CPS) {
        // steal-ahead: grab next chunk id now; latency hides behind chunk
        int nxt = 0;
        if (lane == 0) nxt = atomicAdd(&g_ctr[s], 1);

        const float4* p = shard_base + (long long)rel * CHUNK_F4 + lane;
        float s0 = 0.f, s1 = 0.f, s2 = 0.f, s3 = 0.f;
        #pragma unroll 1
        for (int it = 0; it < CHUNK_F4 / 128; ++it) {      // 8 iters
            float4 a = p[ 0];
            float4 b = p[32];
            float4 c = p[64];
            float4 d = p[96];
            p += 128;
            s0 = fmaf(a.x, a.x, s0);  s1 = fmaf(a.y, a.y, s1);
            s2 = fmaf(a.z, a.z, s2);  s3 = fmaf(a.w, a.w, s3);
            s0 = fmaf(b.x, b.x, s0);  s1 = fmaf(b.y, b.y, s1);
            s2 = fmaf(b.z, b.z, s2);  s3 = fmaf(b.w, b.w, s3);
            s0 = fmaf(c.x, c.x, s0);  s1 = fmaf(c.y, c.y, s1);
            s2 = fmaf(c.z, c.z, s2);  s3 = fmaf(c.w, c.w, s3);
            s0 = fmaf(d.x, d.x, s0);  s1 = fmaf(d.y, d.y, s1);
            s2 = fmaf(d.z, d.z, s2);  s3 = fmaf(d.w, d.w, s3);
        }
        acc += (double)((s0 + s1) + (s2 + s3));

        rel = __shfl_sync(0xffffffffu, nxt, 0);
    }

    // ---- block reduce (double, fixed tree) ----
    #pragma unroll
    for (int o = 16; o > 0; o >>= 1)
        acc += __shfl_xor_sync(0xffffffffu, acc, o);

    __shared__ double wd[NTHREADS / 32];
    __shared__ bool   s_is_last;
    if (lane == 0) wd[wid] = acc;
    __syncthreads();

    if (wid == 0) {
        acc = (lane < NTHREADS / 32) ? wd[lane] : 0.0;
        #pragma unroll
        for (int o = 16; o > 0; o >>= 1)
            acc += __shfl_xor_sync(0xffffffffu, acc, o);
        if (lane == 0) g_partials[blockIdx.x] = acc;   // released by acq_rel
    }

    // ---- last-block election ----
    if (tid == 0) {
        unsigned int ticket;
        asm volatile("atom.add.acq_rel.gpu.u32 %0, [%1], 1;"
                     : "=r"(ticket) : "l"(&g_count) : "memory");
        s_is_last = (ticket == (unsigned int)(gridDim.x - 1));
    }
    __syncthreads();
    if (!s_is_last) return;

    // ---- final: reduce 592 doubles, fixed tree ----
    double dsum = 0.0;
    for (int p = tid; p < NBLOCKS; p += NTHREADS)
        dsum += g_partials[p];

    #pragma unroll
    for (int o = 16; o > 0; o >>= 1)
        dsum += __shfl_xor_sync(0xffffffffu, dsum, o);

    if (lane == 0) wd[wid] = dsum;
    __syncthreads();

    if (wid == 0) {
        dsum = (lane < NTHREADS / 32) ? wd[lane] : 0.0;
        #pragma unroll
        for (int o = 16; o > 0; o >>= 1)
            dsum += __shfl_xor_sync(0xffffffffu, dsum, o);
        if (lane == 0) {
            out[0] = (float)(dsum * (double)scale);
            #pragma unroll
            for (int i = 0; i < SHARDS; ++i) g_ctr[i] = SEEDS;  // replay reset
            g_count = 0;
        }
    }
}

extern "C" void kernel_launch(void* const* d_in, const int* in_sizes, int n_in,
                              void* d_out, int out_size)
{
    const float* x = (const float*)d_in[0];
    long long n = (long long)in_sizes[0];     // 134,217,728
    // exact tiling: 16 shards * 2048 chunks * 1024 float4 = n/4

    // B*C = n / (256*256) = 2048
    float scale = 1.0f / (float)(n / (256LL * 256LL));

    sqsum_ws2_kernel<<<NBLOCKS, NTHREADS>>>((const float4*)x,
                                            (float*)d_out, scale);
}

// round 9
// speedup vs baseline: 1.1649x; 1.1649x over previous
#include <cuda_runtime.h>
#include <cuda_bf16.h>

// NuclearLossFunc: loss = sum(x^2) / (B*C), x: (32,64,256,256) fp32
// = 134,217,728 elements = 512 MiB read. HBM-bound reduction.
//
// R9: CTA-level work stealing (R7's memory-healthy body) with EIGHT
// sharded counters (bid&7). R7's single counter was saturated at ~205
// same-address atomics/us (= why it was neutral); 8 shards cut the per-
// counter rate to ~26/us. Shard s owns a contiguous 64MB region; 74
// CTAs per shard -> SM-speed variance averages out. Straggle bound =
// one 32KB chunk (~2.9us) vs ~7us static finish spread.
// Determinism: fixed tree per chunk; chunk sums in per-thread double;
// fixed final tree in double.

#define NBLOCKS   592           // 148 SMs * 4 CTAs, one wave
#define NTHREADS  512
#define NSHARDS   8
#define CPS       2048          // chunks per shard (16384 total)
#define CHUNK_F4  2048          // 512 thr * 4 float4 = 32KB per chunk
#define CSEED     74            // 592/8 CTAs seed chunks 0..73 per shard

__device__ double       g_partials[NBLOCKS];
__device__ unsigned int g_count;                 // ticket, zero-init
__device__ int g_ctr[NSHARDS] = {
    CSEED, CSEED, CSEED, CSEED, CSEED, CSEED, CSEED, CSEED
};

__global__ __launch_bounds__(NTHREADS) void sqsum_ws3_kernel(
    const float4* __restrict__ in,
    float* __restrict__ out, float scale)
{
    const int tid  = threadIdx.x;
    const int lane = tid & 31;
    const int wid  = tid >> 5;
    const int s    = blockIdx.x & (NSHARDS - 1);
    __shared__ int  s_next[3];
    __shared__ bool s_is_last;

    const float4* shard_base = in + (long long)s * CPS * CHUNK_F4;

    double acc = 0.0;
    int cur = blockIdx.x >> 3;    // shard-local seed chunk 0..73
    int k = 0;

    while (cur < CPS) {
        long long base = (long long)cur * CHUNK_F4 + tid;
        // 4 front-batched coalesced LDG.128 per thread (proven-healthy MLP)
        float4 a = shard_base[base];
        float4 b = shard_base[base +  512];
        float4 c = shard_base[base + 1024];
        float4 d = shard_base[base + 1536];

        // steal next chunk while loads are in flight (per-shard counter)
        if (tid == 0) s_next[(k + 1) % 3] = atomicAdd(&g_ctr[s], 1);

        float s0 = fmaf(a.x, a.x, a.y * a.y);
        float s1 = fmaf(a.z, a.z, a.w * a.w);
        float s2 = fmaf(b.x, b.x, b.y * b.y);
        float s3 = fmaf(b.z, b.z, b.w * b.w);
        s0 = fmaf(c.x, c.x, s0);  s1 = fmaf(c.y, c.y, s1);
        s2 = fmaf(c.z, c.z, s2);  s3 = fmaf(c.w, c.w, s3);
        s0 = fmaf(d.x, d.x, s0);  s1 = fmaf(d.y, d.y, s1);
        s2 = fmaf(d.z, d.z, s2);  s3 = fmaf(d.w, d.w, s3);
        acc += (double)((s0 + s1) + (s2 + s3));

        __syncthreads();                 // publish s_next[(k+1)%3]
        cur = s_next[(k + 1) % 3];       // slot rewritten only at k+3
        k++;
    }

    // ---- block reduce (double, fixed tree) ----
    #pragma unroll
    for (int o = 16; o > 0; o >>= 1)
        acc += __shfl_xor_sync(0xffffffffu, acc, o);

    __shared__ double wd[NTHREADS / 32];
    if (lane == 0) wd[wid] = acc;
    __syncthreads();

    if (wid == 0) {
        acc = (lane < NTHREADS / 32) ? wd[lane] : 0.0;
        #pragma unroll
        for (int o = 16; o > 0; o >>= 1)
            acc += __shfl_xor_sync(0xffffffffu, acc, o);
        if (lane == 0) g_partials[blockIdx.x] = acc;   // released by acq_rel
    }

    // ---- last-block election ----
    if (tid == 0) {
        unsigned int ticket;
        asm volatile("atom.add.acq_rel.gpu.u32 %0, [%1], 1;"
                     : "=r"(ticket) : "l"(&g_count) : "memory");
        s_is_last = (ticket == (unsigned int)(gridDim.x - 1));
    }
    __syncthreads();
    if (!s_is_last) return;

    // ---- final: reduce 592 doubles, fixed tree ----
    double dsum = 0.0;
    for (int p = tid; p < NBLOCKS; p += NTHREADS)
        dsum += g_partials[p];

    #pragma unroll
    for (int o = 16; o > 0; o >>= 1)
        dsum += __shfl_xor_sync(0xffffffffu, dsum, o);

    if (lane == 0) wd[wid] = dsum;
    __syncthreads();

    if (wid == 0) {
        dsum = (lane < NTHREADS / 32) ? wd[lane] : 0.0;
        #pragma unroll
        for (int o = 16; o > 0; o >>= 1)
            dsum += __shfl_xor_sync(0xffffffffu, dsum, o);
        if (lane == 0) {
            out[0] = (float)(dsum * (double)scale);
            #pragma unroll
            for (int i = 0; i < NSHARDS; ++i) g_ctr[i] = CSEED;  // replay reset
            g_count = 0;
        }
    }
}

extern "C" void kernel_launch(void* const* d_in, const int* in_sizes, int n_in,
                              void* d_out, int out_size)
{
    const float* x = (const float*)d_in[0];
    long long n = (long long)in_sizes[0];     // 134,217,728
    // exact tiling: 8 shards * 2048 chunks * 2048 float4 = n/4

    // B*C = n / (256*256) = 2048
    float scale = 1.0f / (float)(n / (256LL * 256LL));

    sqsum_ws3_kernel<<<NBLOCKS, NTHREADS>>>((const float4*)x,
                                            (float*)d_out, scale);
}

// round 10
// speedup vs baseline: 1.1703x; 1.0046x over previous
#include <cuda_runtime.h>
#include <cuda_bf16.h>

// NuclearLossFunc: loss = sum(x^2) / (B*C), x: (32,64,256,256) fp32
// = 134,217,728 elements = 512 MiB read. HBM-bound reduction.
//
// R10: R6 skeleton (best measured: 80.58us kernel, 592x512 single wave,
// fused last-block finalize, acq_rel election) with the hot loop
// upgraded to 256-bit loads (Blackwell LDG.E.256 via 32B-aligned
// ulonglong4). Halves load-issue slots and doubles bytes-in-flight per
// scoreboard slot, targeting the per-warp issue gaps behind the ~15%
// DRAM-idle. Deterministic: fixed tree, final accumulate in double.

#define NBLOCKS  592            // 148 SMs * 4 CTAs -> one wave
#define NTHREADS 512

__device__ double       g_partials[NBLOCKS];
__device__ unsigned int g_count;   // zero-initialized at module load

union V8 {
    ulonglong4 u;               // 32B vector load
    float f[8];
};

__global__ __launch_bounds__(NTHREADS) void sqsum_fused_kernel(
    const ulonglong4* __restrict__ in, long long n8,
    float* __restrict__ out, float scale)
{
    const int lane = threadIdx.x & 31;
    const int wid  = threadIdx.x >> 5;
    __shared__ double wd[NTHREADS / 32];
    __shared__ bool   s_is_last;

    // ---- hot loop: grid-stride, one LDG.E.256 per iteration ----
    float s0 = 0.f, s1 = 0.f, s2 = 0.f, s3 = 0.f;
    long long idx    = (long long)blockIdx.x * blockDim.x + threadIdx.x;
    long long stride = (long long)gridDim.x * blockDim.x;

    for (long long i = idx; i < n8; i += stride) {
        V8 v;
        v.u = in[i];
        s0 = fmaf(v.f[0], v.f[0], s0);
        s1 = fmaf(v.f[1], v.f[1], s1);
        s2 = fmaf(v.f[2], v.f[2], s2);
        s3 = fmaf(v.f[3], v.f[3], s3);
        s0 = fmaf(v.f[4], v.f[4], s0);
        s1 = fmaf(v.f[5], v.f[5], s1);
        s2 = fmaf(v.f[6], v.f[6], s2);
        s3 = fmaf(v.f[7], v.f[7], s3);
    }
    double acc = (double)((s0 + s1) + (s2 + s3));

    // ---- block reduce (double, fixed tree) ----
    #pragma unroll
    for (int o = 16; o > 0; o >>= 1)
        acc += __shfl_xor_sync(0xffffffffu, acc, o);

    if (lane == 0) wd[wid] = acc;
    __syncthreads();

    if (wid == 0) {
        acc = (lane < NTHREADS / 32) ? wd[lane] : 0.0;
        #pragma unroll
        for (int o = 16; o > 0; o >>= 1)
            acc += __shfl_xor_sync(0xffffffffu, acc, o);
        if (lane == 0) g_partials[blockIdx.x] = acc;   // released by acq_rel
    }

    // ---- last-block election: one acq_rel atomic, no fence ----
    if (threadIdx.x == 0) {
        unsigned int ticket;
        asm volatile("atom.add.acq_rel.gpu.u32 %0, [%1], 1;"
                     : "=r"(ticket) : "l"(&g_count) : "memory");
        s_is_last = (ticket == (unsigned int)(gridDim.x - 1));
    }
    __syncthreads();
    if (!s_is_last) return;

    // ---- last block: reduce 592 doubles (deterministic fixed tree) ----
    double dsum = 0.0;
    for (int p = threadIdx.x; p < NBLOCKS; p += NTHREADS)
        dsum += g_partials[p];

    #pragma unroll
    for (int o = 16; o > 0; o >>= 1)
        dsum += __shfl_xor_sync(0xffffffffu, dsum, o);

    if (lane == 0) wd[wid] = dsum;
    __syncthreads();

    if (wid == 0) {
        dsum = (lane < NTHREADS / 32) ? wd[lane] : 0.0;
        #pragma unroll
        for (int o = 16; o > 0; o >>= 1)
            dsum += __shfl_xor_sync(0xffffffffu, dsum, o);
        if (lane == 0) {
            out[0] = (float)(dsum * (double)scale);
            g_count = 0;  // reset for graph replay
        }
    }
}

extern "C" void kernel_launch(void* const* d_in, const int* in_sizes, int n_in,
                              void* d_out, int out_size)
{
    const float* x = (const float*)d_in[0];
    long long n  = (long long)in_sizes[0];    // 134,217,728, divisible by 8
    long long n8 = n >> 3;                    // 16,777,216 x 32B

    // B*C = n / (256*256) = 2048
    float scale = 1.0f / (float)(n / (256LL * 256LL));

    sqsum_fused_kernel<<<NBLOCKS, NTHREADS>>>((const ulonglong4*)x, n8,
                                              (float*)d_out, scale);
}